// round 7
// baseline (speedup 1.0000x reference)
#include <cuda_runtime.h>
#include <cstdint>

#define NTOK 16384
#define DIN 64
#define DOUT 64
#define NC 512
#define KSEL 16
#define NASSIGN (NTOK*KSEL)

typedef unsigned long long u64;

// ---------------- scratch (device globals: no allocation allowed) -------------
__device__ float g_ctrT[DIN*NC];        // centers transposed [k][c]
__device__ float g_scores[NASSIGN];     // softmax scores per (token, j)
__device__ int   g_idx[NASSIGN];        // selected center per (token, j)
__device__ int   g_cnt[NC];
__device__ int   g_off[NC];
__device__ int   g_cursor[NC];
__device__ int   g_tok[NASSIGN];        // bucket -> token id
__device__ float g_ascore[NASSIGN];     // bucket -> score
__device__ int   g_dslot[NASSIGN];      // bucket -> (token*16+j) destination slot
__device__ float g_part[(size_t)NASSIGN*DOUT]; // 67 MB partials, slot-addressed
__device__ float g_c2[NC];              // ||c||^2 + 1024 bias
__device__ int   g_tiles[8192];         // (center, rowStart) pairs
__device__ int   g_ntiles;
__device__ int   g_work;                // dynamic tile cursor for k_gemm
__device__ int   g_flag;                // scan-done flag for k_ss

// ---------------- packed f32x2 helpers ----------------------------------------
__device__ __forceinline__ u64 dupf(float x){
    u64 r; asm("mov.b64 %0, {%1, %1};" : "=l"(r) : "f"(x)); return r;
}
__device__ __forceinline__ void ffma2(u64 &d, u64 a, u64 b){
    asm("fma.rn.f32x2 %0, %1, %2, %0;" : "+l"(d) : "l"(a), "l"(b));
}
__device__ __forceinline__ u64 ffma2v(u64 a, u64 b, u64 c){
    u64 d; asm("fma.rn.f32x2 %0, %1, %2, %3;" : "=l"(d) : "l"(a), "l"(b), "l"(c)); return d;
}
__device__ __forceinline__ u64 fadd2(u64 a, u64 b){
    u64 r; asm("add.rn.f32x2 %0, %1, %2;" : "=l"(r) : "l"(a), "l"(b)); return r;
}
__device__ __forceinline__ u64 fmul2(u64 a, u64 b){
    u64 r; asm("mul.rn.f32x2 %0, %1, %2;" : "=l"(r) : "l"(a), "l"(b)); return r;
}
__device__ __forceinline__ void cpa16(float* dst_smem, const float* src){
    unsigned d = (unsigned)__cvta_generic_to_shared(dst_smem);
    asm volatile("cp.async.cg.shared.global [%0], [%1], 16;" :: "r"(d), "l"(src));
}

// ---------------- K0: transpose centers, c2 (+bias), zero counters -------------
__global__ void k_prep(const float* __restrict__ ctrs){
    int bid = blockIdx.x, tid = threadIdx.x;
    if(bid < 128){
        int e = bid*256 + tid;           // 32768 elements
        int k = e >> 9, c = e & 511;
        g_ctrT[k*NC + c] = ctrs[c*DIN + k];
    } else {
        int c = (bid-128)*256 + tid;     // 512 centers over 2 blocks
        g_cnt[c] = 0;
        if(c == 0){ g_work = 0; g_flag = 0; }
        const float4* c4 = (const float4*)ctrs;
        float s = 1024.0f;  // bias keeps keys > 0; cancels in softmax
        #pragma unroll
        for(int seg=0; seg<16; seg++){
            float4 v = c4[c*16 + seg];
            s += v.x*v.x + v.y*v.y + v.z*v.z + v.w*v.w;
        }
        g_c2[c] = s;
    }
}

// ---------------- K1: fused distance GEMM + top-16 + softmax + counts ----------
// block: 32 tokens x 512 centers.  256 thr = 8 warps; warp w owns 64 centers.
// centers staged through smem in 8-k-row stages via cp.async double buffering.
// thread columns split ogA = w*64+og*4 and ogB = ogA+32: conflict-free LDS.
__global__ __launch_bounds__(256,2) void k_fused(const float* __restrict__ x){
    extern __shared__ char smraw[];
    float* xs  = (float*)smraw;            // 32*64    swizzled x tile
    float* cs2 = xs + 32*64;               // 2 stages of 8*512 centers
    float* ds  = cs2 + 2*8*512;            // 32*512   distance keys
    float* sdf = ds + 32*512;              // 8*16     selected keys
    int*   sci = (int*)(sdf + 8*16);       // 8*16     selected centers

    int tid = threadIdx.x;
    int ttile = blockIdx.x*32;

    // load x tile (32 tokens), swizzled xs[r*64 + (k ^ 8*(r&3))]
    const float4* x4 = (const float4*)x;
    #pragma unroll
    for(int it=0; it<2; it++){
        int idx2 = tid + 256*it;
        int rr = idx2 >> 4, seg = idx2 & 15;
        float4 v = x4[(ttile+rr)*16 + seg];
        *(float4*)&xs[rr*64 + ((seg*4) ^ ((rr&3)*8))] = v;
    }

    // prologue: async-stage k rows 0..7
    #pragma unroll
    for(int i=0;i<4;i++){
        int e = tid + 256*i;               // 0..1023 float4 slots
        int row = e >> 7, c4i = e & 127;
        cpa16(&cs2[row*NC + c4i*4], &g_ctrT[row*NC + c4i*4]);
    }
    asm volatile("cp.async.commit_group;");

    int w  = tid >> 5, lane = tid & 31;
    int og = lane & 7, tg = lane >> 3;     // tg in 0..3
    int cbA = w*64 + og*4;                 // first 4-center group
    int cbB = cbA + 32;                    // second 4-center group
    int xsw = tg*8;

    u64 acc[8][4];
    #pragma unroll
    for(int i=0;i<8;i++){ acc[i][0]=0; acc[i][1]=0; acc[i][2]=0; acc[i][3]=0; }

    #pragma unroll 1
    for(int s=0; s<8; s++){
        __syncthreads();                   // all done with buf^1 from stage s-1
        if(s < 7){
            float* nb = cs2 + ((s+1)&1)*4096;
            const float* src = g_ctrT + (s+1)*8*NC;
            #pragma unroll
            for(int i=0;i<4;i++){
                int e = tid + 256*i;
                int row = e >> 7, c4i = e & 127;
                cpa16(&nb[row*NC + c4i*4], &src[row*NC + c4i*4]);
            }
            asm volatile("cp.async.commit_group;");
            asm volatile("cp.async.wait_group 1;");
        } else {
            asm volatile("cp.async.wait_group 0;");
        }
        __syncthreads();                   // stage s visible to all

        float* cs = cs2 + (s&1)*4096;
        #pragma unroll
        for(int k4=0;k4<2;k4++){
            float v4[8][4];
            #pragma unroll
            for(int i=0;i<8;i++)
                *(float4*)v4[i] =
                    *(const float4*)&xs[(tg+4*i)*64 + (((s*8+k4*4)) ^ xsw)];
            #pragma unroll
            for(int kk=0;kk<4;kk++){
                int kl = k4*4 + kk;
                ulonglong2 p0 = *(const ulonglong2*)&cs[kl*NC + cbA];
                ulonglong2 p1 = *(const ulonglong2*)&cs[kl*NC + cbB];
                #pragma unroll
                for(int i=0;i<8;i++){
                    u64 xv = dupf(v4[i][kk]);
                    ffma2(acc[i][0], xv, p0.x);
                    ffma2(acc[i][1], xv, p0.y);
                    ffma2(acc[i][2], xv, p1.x);
                    ffma2(acc[i][3], xv, p1.y);
                }
            }
        }
    }
    // key = c2b - 2*(x.c), write to ds
    {
        ulonglong2 q0 = *(const ulonglong2*)&g_c2[cbA];
        ulonglong2 q1 = *(const ulonglong2*)&g_c2[cbB];
        u64 m2 = dupf(-2.0f);
        #pragma unroll
        for(int i=0;i<8;i++){
            int r = tg + 4*i;
            *(ulonglong2*)&ds[r*NC + cbA] =
                make_ulonglong2(ffma2v(acc[i][0], m2, q0.x),
                                ffma2v(acc[i][1], m2, q0.y));
            *(ulonglong2*)&ds[r*NC + cbB] =
                make_ulonglong2(ffma2v(acc[i][2], m2, q1.x),
                                ffma2v(acc[i][3], m2, q1.y));
        }
    }
    __syncthreads();

    // top-16 per token: warp w handles tokens w*4..w*4+3 (stride-32: conflict-free)
    float* sd  = sdf + w*16;
    int*   sc  = sci + w*16;
    for(int tt=0; tt<4; tt++){
        int t = w*4 + tt;
        float v[16];
        #pragma unroll
        for(int i=0;i<16;i++) v[i] = ds[t*NC + lane + 32*i];

        float lmin = v[0]; int larg = 0;
        #pragma unroll
        for(int i=1;i<16;i++){ if(v[i] < lmin){ lmin=v[i]; larg=i; } }

        #pragma unroll 1
        for(int j=0;j<16;j++){
            // keys > 0 so float bits order-preserve as unsigned
            unsigned mb   = __reduce_min_sync(0xffffffffu, __float_as_uint(lmin));
            unsigned ball = __ballot_sync(0xffffffffu, __float_as_uint(lmin) == mb);
            int wlan = __ffs(ball) - 1;
            if(lane == wlan){
                sd[j] = lmin;
                sc[j] = larg*32 + lane;
                v[larg] = 3.0e38f;
                lmin = v[0]; larg = 0;
                #pragma unroll
                for(int i=1;i<16;i++){ if(v[i] < lmin){ lmin=v[i]; larg=i; } }
            }
            __syncwarp();
        }
        if(lane < 16){
            float d = sd[lane];
            float m = sd[0];
            float e = expf(m - d);
            float s = e;
            #pragma unroll
            for(int o=8;o>=1;o>>=1) s += __shfl_xor_sync(0x0000ffffu, s, o);
            float scv = e / s;
            int c = sc[lane];
            int gt = ttile + t;
            g_scores[gt*16 + lane] = scv;
            g_idx[gt*16 + lane]    = c;
            atomicAdd(&g_cnt[c], 1);
        }
        __syncwarp();
    }
}

// ---------------- K2: fused scan (block 0) + scatter (all 512 blocks) ----------
__global__ __launch_bounds__(512) void k_ss(){
    __shared__ int wsum[16];
    int tid = threadIdx.x;

    if(blockIdx.x == 0){
        int c = tid, lane = c & 31, w = c >> 5;
        int cn = g_cnt[c];
        int s = cn;
        #pragma unroll
        for(int o=1;o<32;o<<=1){ int v=__shfl_up_sync(0xffffffffu,s,o); if(lane>=o) s+=v; }
        if(lane==31) wsum[w] = s;
        __syncthreads();
        if(w==0){
            int t = (lane<16) ? wsum[lane] : 0;
            #pragma unroll
            for(int o=1;o<16;o<<=1){ int v=__shfl_up_sync(0xffffffffu,t,o); if(lane>=o) t+=v; }
            if(lane<16) wsum[lane] = t;
        }
        __syncthreads();
        int inc = s + ((w>0) ? wsum[w-1] : 0);
        g_off[c] = inc - cn;
        g_cursor[c] = inc - cn;

        int t = (cn + 127) >> 7;
        __syncthreads();
        int s2 = t;
        #pragma unroll
        for(int o=1;o<32;o<<=1){ int v=__shfl_up_sync(0xffffffffu,s2,o); if(lane>=o) s2+=v; }
        if(lane==31) wsum[w] = s2;
        __syncthreads();
        if(w==0){
            int tt = (lane<16) ? wsum[lane] : 0;
            #pragma unroll
            for(int o=1;o<16;o<<=1){ int v=__shfl_up_sync(0xffffffffu,tt,o); if(lane>=o) tt+=v; }
            if(lane<16) wsum[lane] = tt;
        }
        __syncthreads();
        int tinc = s2 + ((w>0) ? wsum[w-1] : 0);
        int tb = tinc - t;
        for(int i=0;i<t;i++){
            g_tiles[2*(tb+i)]   = c;
            g_tiles[2*(tb+i)+1] = i << 7;
        }
        if(c == 511) g_ntiles = tinc;
        __threadfence();
        __syncthreads();
        if(tid == 0) *((volatile int*)&g_flag) = 1;
    } else {
        if(tid == 0){ while(*((volatile int*)&g_flag) == 0){ } }
        __syncthreads();
    }

    int a = blockIdx.x*512 + tid;          // (token<<4)|j
    int c = g_idx[a];
    float s = g_scores[a];
    int pos = atomicAdd(&g_cursor[c], 1);
    g_tok[pos]   = a >> 4;
    g_ascore[pos]= s;
    g_dslot[pos] = a;
}

// ---------------- K3: grouped GEMM per (center, 128-row tile) ------------------
// R5 configuration: 256 thr, thread tile 4 rows x 8 cols (split og*4 / og*4+32).
// Warp w owns rows [16w, 16w+16): whole-warp skip when 16w >= m.
__global__ __launch_bounds__(256,3) void k_gemm(const float* __restrict__ x,
                                                const float* __restrict__ Wv,
                                                const float* __restrict__ Ov){
    __shared__ float ws[DIN*DOUT];   // ws[k*64 + p] (row-major copy of Wv[c])
    __shared__ float xs[128*DIN];    // xs[r*64 + (k ^ 8*((r>>2)&3))]
    __shared__ int s_tile;
    int nt = g_ntiles;
    int tid = threadIdx.x;
    int og = tid & 7, tg = tid >> 3;     // tg 0..31
    int w  = tid >> 5;
    int xsw = (tg & 3) * 8;              // rows tg*4..tg*4+3 share (r>>2)&3 == tg&3
    const float4* x4 = (const float4*)x;

    while(true){
        __syncthreads();             // smem reuse + s_tile protection
        if(tid == 0) s_tile = atomicAdd(&g_work, 1);
        __syncthreads();
        int tile = s_tile;
        if(tile >= nt) break;

        int c      = g_tiles[2*tile];
        int rstart = g_tiles[2*tile+1];
        int base   = g_off[c] + rstart;
        int m      = g_cnt[c] - rstart; if(m > 128) m = 128;

        const float4* wv4 = (const float4*)(Wv + (size_t)c*4096);
        float4* ws4 = (float4*)ws;
        #pragma unroll
        for(int f=0; f<4; f++) ws4[tid + 256*f] = wv4[tid + 256*f];

        #pragma unroll
        for(int it=0; it<8; it++){
            int idx2 = tid + 256*it;
            int rr = idx2 >> 4, seg = idx2 & 15;
            if(rr < m){
                float4 v = x4[g_tok[base+rr]*16 + seg];
                *(float4*)&xs[rr*64 + ((seg*4) ^ (((rr>>2)&3)*8))] = v;
            }
        }
        __syncthreads();

        if(16*w < m){                   // warp-uniform: skip padded rows
            u64 acc[4][4];
            #pragma unroll
            for(int i=0;i<4;i++){ acc[i][0]=0; acc[i][1]=0; acc[i][2]=0; acc[i][3]=0; }

            #pragma unroll 4
            for(int k4=0;k4<16;k4++){
                float v4[4][4];
                #pragma unroll
                for(int i=0;i<4;i++)
                    *(float4*)v4[i] = *(const float4*)&xs[(tg*4+i)*64 + ((k4*4) ^ xsw)];
                #pragma unroll
                for(int kk=0;kk<4;kk++){
                    int k = k4*4 + kk;
                    ulonglong2 p0 = *(const ulonglong2*)&ws[k*64 + og*4];
                    ulonglong2 p1 = *(const ulonglong2*)&ws[k*64 + og*4 + 32];
                    #pragma unroll
                    for(int i=0;i<4;i++){
                        u64 xv = dupf(v4[i][kk]);
                        ffma2(acc[i][0], xv, p0.x);
                        ffma2(acc[i][1], xv, p0.y);
                        ffma2(acc[i][2], xv, p1.x);
                        ffma2(acc[i][3], xv, p1.y);
                    }
                }
            }
            ulonglong2 q0 = *(const ulonglong2*)&Ov[(size_t)c*64 + og*4];
            ulonglong2 q1 = *(const ulonglong2*)&Ov[(size_t)c*64 + og*4 + 32];
            #pragma unroll
            for(int i=0;i<4;i++){
                int r = tg*4 + i;
                if(r < m){
                    int slot = g_dslot[base + r];
                    u64 sv = dupf(g_ascore[base + r]);
                    ulonglong2* d0 = (ulonglong2*)&g_part[(size_t)slot*64 + og*4];
                    ulonglong2* d1 = (ulonglong2*)&g_part[(size_t)slot*64 + og*4 + 32];
                    *d0 = make_ulonglong2(fmul2(fadd2(acc[i][0], q0.x), sv),
                                          fmul2(fadd2(acc[i][1], q0.y), sv));
                    *d1 = make_ulonglong2(fmul2(fadd2(acc[i][2], q1.x), sv),
                                          fmul2(fadd2(acc[i][3], q1.y), sv));
                }
            }
        }
    }
}

// ---------------- K4: streamed reduce of 16 contiguous partials per token ------
__global__ __launch_bounds__(256) void k_reduce(float* __restrict__ out){
    int t  = blockIdx.x*16 + (threadIdx.x >> 4);
    int c4 = threadIdx.x & 15;
    const float4* p = (const float4*)(g_part + (size_t)t*16*64) + c4;
    float4 acc = make_float4(0.f,0.f,0.f,0.f);
    #pragma unroll
    for(int j=0;j<16;j++){
        float4 v = p[j*16];
        acc.x += v.x; acc.y += v.y; acc.z += v.z; acc.w += v.w;
    }
    ((float4*)out)[t*16 + c4] = acc;
}

// ---------------- launch -------------------------------------------------------
extern "C" void kernel_launch(void* const* d_in, const int* in_sizes, int n_in,
                              void* d_out, int out_size){
    const float* x    = (const float*)d_in[0];
    const float* ctrs = (const float*)d_in[1];
    const float* Wv   = (const float*)d_in[2];
    const float* Ov   = (const float*)d_in[3];
    float* out = (float*)d_out;

    const int FUSED_SMEM = (32*64 + 2*8*512 + 32*512 + 8*16)*4 + 8*16*4;
    cudaFuncSetAttribute(k_fused, cudaFuncAttributeMaxDynamicSharedMemorySize,
                         FUSED_SMEM);

    k_prep  <<<130, 256>>>(ctrs);
    k_fused <<<512, 256, FUSED_SMEM>>>(x);
    k_ss    <<<512, 512>>>();
    k_gemm  <<<444, 256>>>(x, Wv, Ov);
    k_reduce<<<1024, 256>>>(out);
}

// round 8
// speedup vs baseline: 1.0537x; 1.0537x over previous
#include <cuda_runtime.h>
#include <cstdint>

#define NTOK 16384
#define DIN 64
#define DOUT 64
#define NC 512
#define KSEL 16
#define NASSIGN (NTOK*KSEL)

typedef unsigned long long u64;

// ---------------- scratch (device globals: no allocation allowed) -------------
__device__ float g_ctrT[DIN*NC];        // centers transposed [k][c]
__device__ float g_scores[NASSIGN];     // softmax scores per (token, j)
__device__ int   g_idx[NASSIGN];        // selected center per (token, j)
__device__ int   g_cnt[NC];
__device__ int   g_off[NC];
__device__ int   g_cursor[NC];
__device__ int   g_tok[NASSIGN];        // bucket -> token id
__device__ float g_ascore[NASSIGN];     // bucket -> score
__device__ int   g_dslot[NASSIGN];      // bucket -> (token*16+j) destination slot
__device__ float g_part[(size_t)NASSIGN*DOUT]; // 67 MB partials, slot-addressed
__device__ float g_c2[NC];              // ||c||^2 + 1024 bias
__device__ int   g_tiles[8192];         // (center, rowStart) pairs
__device__ int   g_ntiles;
__device__ int   g_work;                // dynamic tile cursor for k_gemm
__device__ int   g_flag;                // scan-done flag for k_ss

// ---------------- packed f32x2 helpers ----------------------------------------
__device__ __forceinline__ u64 dupf(float x){
    u64 r; asm("mov.b64 %0, {%1, %1};" : "=l"(r) : "f"(x)); return r;
}
__device__ __forceinline__ void ffma2(u64 &d, u64 a, u64 b){
    asm("fma.rn.f32x2 %0, %1, %2, %0;" : "+l"(d) : "l"(a), "l"(b));
}
__device__ __forceinline__ u64 ffma2v(u64 a, u64 b, u64 c){
    u64 d; asm("fma.rn.f32x2 %0, %1, %2, %3;" : "=l"(d) : "l"(a), "l"(b), "l"(c)); return d;
}
__device__ __forceinline__ u64 fadd2(u64 a, u64 b){
    u64 r; asm("add.rn.f32x2 %0, %1, %2;" : "=l"(r) : "l"(a), "l"(b)); return r;
}
__device__ __forceinline__ u64 fmul2(u64 a, u64 b){
    u64 r; asm("mul.rn.f32x2 %0, %1, %2;" : "=l"(r) : "l"(a), "l"(b)); return r;
}

// ---------------- K0a: transpose centers ---------------------------------------
__global__ void k_prep_t(const float* __restrict__ ctrs){
    int e = blockIdx.x*256 + threadIdx.x;   // 32768 elements
    int k = e >> 9, c = e & 511;
    g_ctrT[k*NC + c] = ctrs[c*DIN + k];
}

// ---------------- K0b: c2 (+bias) ----------------------------------------------
__global__ void k_prep_c(const float* __restrict__ ctrs){
    int c = blockIdx.x*256 + threadIdx.x;   // 512 centers
    const float4* c4 = (const float4*)ctrs;
    float s = 1024.0f;  // bias keeps keys > 0; cancels in softmax
    #pragma unroll
    for(int seg=0; seg<16; seg++){
        float4 v = c4[c*16 + seg];
        s += v.x*v.x + v.y*v.y + v.z*v.z + v.w*v.w;
    }
    g_c2[c] = s;
}

// ---------------- K0c: zero counters -------------------------------------------
__global__ void k_prep_z(){
    int c = blockIdx.x*256 + threadIdx.x;
    g_cnt[c] = 0;
    if(c == 0){ g_work = 0; g_flag = 0; }
}

// ---------------- K1: fused distance GEMM + top-16 + softmax + counts ----------
// block: 32 tokens x 512 centers.  512 thr = 16 warps; warp w owns 32 centers.
// lane: og = lane&7 (8 groups of 4 centers), tg = lane>>3 (tokens tg+4i, i<8).
// acc = 16 u64 regs/thread: low pressure, no spills, deep ILP.
__global__ __launch_bounds__(512,1) void k_fused(const float* __restrict__ x){
    extern __shared__ char smraw[];
    float* xs  = (float*)smraw;            // 32*64    swizzled x tile
    float* ds  = xs + 32*64;               // 32*512   distance keys
    float* sdf = ds + 32*512;              // 16*16    selected keys
    int*   sci = (int*)(sdf + 16*16);      // 16*16    selected centers

    int tid = threadIdx.x;
    int ttile = blockIdx.x*32;

    // load x tile (32 tokens), swizzled xs[r*64 + (k ^ 8*(r&3))]
    const float4* x4 = (const float4*)x;
    {
        int rr = tid >> 4, seg = tid & 15;
        float4 v = x4[(ttile+rr)*16 + seg];
        *(float4*)&xs[rr*64 + ((seg*4) ^ ((rr&3)*8))] = v;
    }
    __syncthreads();

    int w  = tid >> 5, lane = tid & 31;
    int og = lane & 7, tg = lane >> 3;     // tg in 0..3
    int cb = w*32 + og*4;                  // this thread's 4 centers
    int xsw = tg*8;

    u64 acc[8][2];
    #pragma unroll
    for(int i=0;i<8;i++){ acc[i][0]=0; acc[i][1]=0; }

    #pragma unroll 2
    for(int k4=0;k4<16;k4++){
        float v4[8][4];
        #pragma unroll
        for(int i=0;i<8;i++)
            *(float4*)v4[i] = *(const float4*)&xs[(tg+4*i)*64 + ((k4*4) ^ xsw)];
        #pragma unroll
        for(int kk=0;kk<4;kk++){
            int k = k4*4 + kk;
            ulonglong2 p0 = *(const ulonglong2*)&g_ctrT[k*NC + cb];
            #pragma unroll
            for(int i=0;i<8;i++){
                u64 xv = dupf(v4[i][kk]);
                ffma2(acc[i][0], xv, p0.x);
                ffma2(acc[i][1], xv, p0.y);
            }
        }
    }
    // key = c2b - 2*(x.c), write to ds
    {
        ulonglong2 q0 = *(const ulonglong2*)&g_c2[cb];
        u64 m2 = dupf(-2.0f);
        #pragma unroll
        for(int i=0;i<8;i++){
            int r = tg + 4*i;
            *(ulonglong2*)&ds[r*NC + cb] =
                make_ulonglong2(ffma2v(acc[i][0], m2, q0.x),
                                ffma2v(acc[i][1], m2, q0.y));
        }
    }
    __syncthreads();

    // top-16 per token: warp w handles tokens w*2, w*2+1 (stride-32: conflict-free)
    float* sd  = sdf + w*16;
    int*   sc  = sci + w*16;
    for(int tt=0; tt<2; tt++){
        int t = w*2 + tt;
        float v[16];
        #pragma unroll
        for(int i=0;i<16;i++) v[i] = ds[t*NC + lane + 32*i];

        float lmin = v[0]; int larg = 0;
        #pragma unroll
        for(int i=1;i<16;i++){ if(v[i] < lmin){ lmin=v[i]; larg=i; } }

        #pragma unroll 1
        for(int j=0;j<16;j++){
            // keys > 0 so float bits order-preserve as unsigned
            unsigned mb   = __reduce_min_sync(0xffffffffu, __float_as_uint(lmin));
            unsigned ball = __ballot_sync(0xffffffffu, __float_as_uint(lmin) == mb);
            int wlan = __ffs(ball) - 1;
            if(lane == wlan){
                sd[j] = lmin;
                sc[j] = larg*32 + lane;
                v[larg] = 3.0e38f;
                lmin = v[0]; larg = 0;
                #pragma unroll
                for(int i=1;i<16;i++){ if(v[i] < lmin){ lmin=v[i]; larg=i; } }
            }
            __syncwarp();
        }
        if(lane < 16){
            float d = sd[lane];
            float m = sd[0];
            float e = expf(m - d);
            float s = e;
            #pragma unroll
            for(int o=8;o>=1;o>>=1) s += __shfl_xor_sync(0x0000ffffu, s, o);
            float scv = e / s;
            int c = sc[lane];
            int gt = ttile + t;
            g_scores[gt*16 + lane] = scv;
            g_idx[gt*16 + lane]    = c;
            atomicAdd(&g_cnt[c], 1);
        }
        __syncwarp();
    }
}

// ---------------- K2: fused scan (block 0) + scatter (all 512 blocks) ----------
__global__ __launch_bounds__(512) void k_ss(){
    __shared__ int wsum[16];
    int tid = threadIdx.x;

    if(blockIdx.x == 0){
        int c = tid, lane = c & 31, w = c >> 5;
        int cn = g_cnt[c];
        int s = cn;
        #pragma unroll
        for(int o=1;o<32;o<<=1){ int v=__shfl_up_sync(0xffffffffu,s,o); if(lane>=o) s+=v; }
        if(lane==31) wsum[w] = s;
        __syncthreads();
        if(w==0){
            int t = (lane<16) ? wsum[lane] : 0;
            #pragma unroll
            for(int o=1;o<16;o<<=1){ int v=__shfl_up_sync(0xffffffffu,t,o); if(lane>=o) t+=v; }
            if(lane<16) wsum[lane] = t;
        }
        __syncthreads();
        int inc = s + ((w>0) ? wsum[w-1] : 0);
        g_off[c] = inc - cn;
        g_cursor[c] = inc - cn;

        int t = (cn + 127) >> 7;
        __syncthreads();
        int s2 = t;
        #pragma unroll
        for(int o=1;o<32;o<<=1){ int v=__shfl_up_sync(0xffffffffu,s2,o); if(lane>=o) s2+=v; }
        if(lane==31) wsum[w] = s2;
        __syncthreads();
        if(w==0){
            int tt = (lane<16) ? wsum[lane] : 0;
            #pragma unroll
            for(int o=1;o<16;o<<=1){ int v=__shfl_up_sync(0xffffffffu,tt,o); if(lane>=o) tt+=v; }
            if(lane<16) wsum[lane] = tt;
        }
        __syncthreads();
        int tinc = s2 + ((w>0) ? wsum[w-1] : 0);
        int tb = tinc - t;
        for(int i=0;i<t;i++){
            g_tiles[2*(tb+i)]   = c;
            g_tiles[2*(tb+i)+1] = i << 7;
        }
        if(c == 511) g_ntiles = tinc;
        __threadfence();
        __syncthreads();
        if(tid == 0) *((volatile int*)&g_flag) = 1;
    } else {
        if(tid == 0){ while(*((volatile int*)&g_flag) == 0){ } }
        __syncthreads();
    }

    int a = blockIdx.x*512 + tid;          // (token<<4)|j
    int c = g_idx[a];
    float s = g_scores[a];
    int pos = atomicAdd(&g_cursor[c], 1);
    g_tok[pos]   = a >> 4;
    g_ascore[pos]= s;
    g_dslot[pos] = a;
}

// ---------------- K3: grouped GEMM per (center, 128-row tile) ------------------
// 256 thr, thread tile 4 rows x 8 cols (split og*4 / og*4+32).
// Warp w owns rows [16w, 16w+16): whole-warp skip when 16w >= m.
__global__ __launch_bounds__(256,3) void k_gemm(const float* __restrict__ x,
                                                const float* __restrict__ Wv,
                                                const float* __restrict__ Ov){
    __shared__ float ws[DIN*DOUT];   // ws[k*64 + p] (row-major copy of Wv[c])
    __shared__ float xs[128*DIN];    // xs[r*64 + (k ^ 8*((r>>2)&3))]
    __shared__ int s_tile;
    int nt = g_ntiles;
    int tid = threadIdx.x;
    int og = tid & 7, tg = tid >> 3;     // tg 0..31
    int w  = tid >> 5;
    int xsw = (tg & 3) * 8;              // rows tg*4..tg*4+3 share (r>>2)&3 == tg&3
    const float4* x4 = (const float4*)x;

    while(true){
        __syncthreads();             // smem reuse + s_tile protection
        if(tid == 0) s_tile = atomicAdd(&g_work, 1);
        __syncthreads();
        int tile = s_tile;
        if(tile >= nt) break;

        int c      = g_tiles[2*tile];
        int rstart = g_tiles[2*tile+1];
        int base   = g_off[c] + rstart;
        int m      = g_cnt[c] - rstart; if(m > 128) m = 128;

        const float4* wv4 = (const float4*)(Wv + (size_t)c*4096);
        float4* ws4 = (float4*)ws;
        #pragma unroll
        for(int f=0; f<4; f++) ws4[tid + 256*f] = wv4[tid + 256*f];

        #pragma unroll
        for(int it=0; it<8; it++){
            int idx2 = tid + 256*it;
            int rr = idx2 >> 4, seg = idx2 & 15;
            if(rr < m){
                float4 v = x4[g_tok[base+rr]*16 + seg];
                *(float4*)&xs[rr*64 + ((seg*4) ^ (((rr>>2)&3)*8))] = v;
            }
        }
        __syncthreads();

        if(16*w < m){                   // warp-uniform: skip padded rows
            u64 acc[4][4];
            #pragma unroll
            for(int i=0;i<4;i++){ acc[i][0]=0; acc[i][1]=0; acc[i][2]=0; acc[i][3]=0; }

            #pragma unroll 4
            for(int k4=0;k4<16;k4++){
                float v4[4][4];
                #pragma unroll
                for(int i=0;i<4;i++)
                    *(float4*)v4[i] = *(const float4*)&xs[(tg*4+i)*64 + ((k4*4) ^ xsw)];
                #pragma unroll
                for(int kk=0;kk<4;kk++){
                    int k = k4*4 + kk;
                    ulonglong2 p0 = *(const ulonglong2*)&ws[k*64 + og*4];
                    ulonglong2 p1 = *(const ulonglong2*)&ws[k*64 + og*4 + 32];
                    #pragma unroll
                    for(int i=0;i<4;i++){
                        u64 xv = dupf(v4[i][kk]);
                        ffma2(acc[i][0], xv, p0.x);
                        ffma2(acc[i][1], xv, p0.y);
                        ffma2(acc[i][2], xv, p1.x);
                        ffma2(acc[i][3], xv, p1.y);
                    }
                }
            }
            ulonglong2 q0 = *(const ulonglong2*)&Ov[(size_t)c*64 + og*4];
            ulonglong2 q1 = *(const ulonglong2*)&Ov[(size_t)c*64 + og*4 + 32];
            #pragma unroll
            for(int i=0;i<4;i++){
                int r = tg*4 + i;
                if(r < m){
                    int slot = g_dslot[base + r];
                    u64 sv = dupf(g_ascore[base + r]);
                    ulonglong2* d0 = (ulonglong2*)&g_part[(size_t)slot*64 + og*4];
                    ulonglong2* d1 = (ulonglong2*)&g_part[(size_t)slot*64 + og*4 + 32];
                    *d0 = make_ulonglong2(fmul2(fadd2(acc[i][0], q0.x), sv),
                                          fmul2(fadd2(acc[i][1], q0.y), sv));
                    *d1 = make_ulonglong2(fmul2(fadd2(acc[i][2], q1.x), sv),
                                          fmul2(fadd2(acc[i][3], q1.y), sv));
                }
            }
        }
    }
}

// ---------------- K4: streamed reduce of 16 contiguous partials per token ------
__global__ __launch_bounds__(256) void k_reduce(float* __restrict__ out){
    int t  = blockIdx.x*16 + (threadIdx.x >> 4);
    int c4 = threadIdx.x & 15;
    const float4* p = (const float4*)(g_part + (size_t)t*16*64) + c4;
    float4 acc = make_float4(0.f,0.f,0.f,0.f);
    #pragma unroll
    for(int j=0;j<16;j++){
        float4 v = p[j*16];
        acc.x += v.x; acc.y += v.y; acc.z += v.z; acc.w += v.w;
    }
    ((float4*)out)[t*16 + c4] = acc;
}

// ---------------- launch -------------------------------------------------------
extern "C" void kernel_launch(void* const* d_in, const int* in_sizes, int n_in,
                              void* d_out, int out_size){
    const float* x    = (const float*)d_in[0];
    const float* ctrs = (const float*)d_in[1];
    const float* Wv   = (const float*)d_in[2];
    const float* Ov   = (const float*)d_in[3];
    float* out = (float*)d_out;

    const int FUSED_SMEM = (32*64 + 32*512 + 16*16)*4 + 16*16*4;
    cudaFuncSetAttribute(k_fused, cudaFuncAttributeMaxDynamicSharedMemorySize,
                         FUSED_SMEM);

    k_prep_t<<<128, 256>>>(ctrs);
    k_prep_c<<<2, 256>>>(ctrs);
    k_prep_z<<<2, 256>>>();
    k_fused <<<512, 512, FUSED_SMEM>>>(x);   // launch #4 -> ncu capture target
    k_ss    <<<512, 512>>>();
    k_gemm  <<<444, 256>>>(x, Wv, Ov);
    k_reduce<<<1024, 256>>>(out);
}

// round 9
// speedup vs baseline: 1.0659x; 1.0116x over previous
#include <cuda_runtime.h>
#include <cstdint>

#define NTOK 16384
#define DIN 64
#define DOUT 64
#define NC 512
#define KSEL 16
#define NASSIGN (NTOK*KSEL)

typedef unsigned long long u64;
typedef unsigned int u32;

// ---------------- scratch (device globals: no allocation allowed) -------------
__device__ float g_ctrT[DIN*NC];        // centers transposed [k][c]
__device__ float g_scores[NASSIGN];     // softmax scores per (token, j)
__device__ int   g_idx[NASSIGN];        // selected center per (token, j)
__device__ int   g_cnt[NC];
__device__ int   g_off[NC];
__device__ int   g_cursor[NC];
__device__ int   g_tok[NASSIGN];        // bucket -> token id
__device__ float g_ascore[NASSIGN];     // bucket -> score
__device__ int   g_dslot[NASSIGN];      // bucket -> (token*16+j) destination slot
__device__ float g_part[(size_t)NASSIGN*DOUT]; // 67 MB partials, slot-addressed
__device__ float g_c2[NC];              // ||c||^2 + 1024 bias
__device__ int   g_tiles[8192];         // (center, rowStart) pairs
__device__ int   g_ntiles;
__device__ int   g_work;                // dynamic tile cursor for k_gemm
__device__ int   g_flag;                // scan-done flag for k_ss

// ---------------- packed f32x2 helpers ----------------------------------------
__device__ __forceinline__ u64 dupf(float x){
    u64 r; asm("mov.b64 %0, {%1, %1};" : "=l"(r) : "f"(x)); return r;
}
__device__ __forceinline__ void ffma2(u64 &d, u64 a, u64 b){
    asm("fma.rn.f32x2 %0, %1, %2, %0;" : "+l"(d) : "l"(a), "l"(b));
}
__device__ __forceinline__ u64 ffma2v(u64 a, u64 b, u64 c){
    u64 d; asm("fma.rn.f32x2 %0, %1, %2, %3;" : "=l"(d) : "l"(a), "l"(b), "l"(c)); return d;
}
__device__ __forceinline__ u64 fadd2(u64 a, u64 b){
    u64 r; asm("add.rn.f32x2 %0, %1, %2;" : "=l"(r) : "l"(a), "l"(b)); return r;
}
__device__ __forceinline__ u64 fmul2(u64 a, u64 b){
    u64 r; asm("mul.rn.f32x2 %0, %1, %2;" : "=l"(r) : "l"(a), "l"(b)); return r;
}

// bitonic sort 16 u64 ascending, fully unrolled, register-resident
#define BITONIC16(P) do{ \
    _Pragma("unroll") \
    for(int k_=2;k_<=16;k_<<=1){ \
        _Pragma("unroll") \
        for(int j_=k_>>1;j_>0;j_>>=1){ \
            _Pragma("unroll") \
            for(int i_=0;i_<16;i_++){ \
                int l_=i_^j_; \
                if(l_>i_){ \
                    bool up_=((i_&k_)==0); \
                    u64 a_=P[i_], b_=P[l_]; \
                    bool sw_= up_ ? (a_>b_) : (a_<b_); \
                    if(sw_){ P[i_]=b_; P[l_]=a_; } \
                } \
            } \
        } \
    } }while(0)

// ---------------- K0a: transpose centers ---------------------------------------
__global__ void k_prep_t(const float* __restrict__ ctrs){
    int e = blockIdx.x*256 + threadIdx.x;   // 32768 elements
    int k = e >> 9, c = e & 511;
    g_ctrT[k*NC + c] = ctrs[c*DIN + k];
}

// ---------------- K0b: c2 (+bias) ----------------------------------------------
__global__ void k_prep_c(const float* __restrict__ ctrs){
    int c = blockIdx.x*256 + threadIdx.x;   // 512 centers
    const float4* c4 = (const float4*)ctrs;
    float s = 1024.0f;  // bias keeps keys > 0; cancels in softmax
    #pragma unroll
    for(int seg=0; seg<16; seg++){
        float4 v = c4[c*16 + seg];
        s += v.x*v.x + v.y*v.y + v.z*v.z + v.w*v.w;
    }
    g_c2[c] = s;
}

// ---------------- K0c: zero counters -------------------------------------------
__global__ void k_prep_z(){
    int c = blockIdx.x*256 + threadIdx.x;
    g_cnt[c] = 0;
    if(c == 0){ g_work = 0; g_flag = 0; }
}

// ---------------- K1: fused distance GEMM + branchless top-16 + softmax --------
// block: 32 tokens x 512 centers.  512 thr = 16 warps; warp w owns 32 centers.
// selection: per-lane bitonic-sorted candidates, O(1) predicated pops.
__global__ __launch_bounds__(512,1) void k_fused(const float* __restrict__ x){
    extern __shared__ char smraw[];
    float* xs  = (float*)smraw;            // 32*64    swizzled x tile (8KB)
    float* ds  = xs + 32*64;               // 32*512   distance keys   (64KB)
    u64*   Pb  = (u64*)(ds + 32*512);      // 16 warps * 2 tok * 512   (128KB)

    int tid = threadIdx.x;
    int ttile = blockIdx.x*32;

    // load x tile (32 tokens), swizzled xs[r*64 + (k ^ 8*(r&3))]
    const float4* x4 = (const float4*)x;
    {
        int rr = tid >> 4, seg = tid & 15;
        float4 v = x4[(ttile+rr)*16 + seg];
        *(float4*)&xs[rr*64 + ((seg*4) ^ ((rr&3)*8))] = v;
    }
    __syncthreads();

    int w  = tid >> 5, lane = tid & 31;
    int og = lane & 7, tg = lane >> 3;     // tg in 0..3
    int cb = w*32 + og*4;                  // this thread's 4 centers
    int xsw = tg*8;

    u64 acc[8][2];
    #pragma unroll
    for(int i=0;i<8;i++){ acc[i][0]=0; acc[i][1]=0; }

    #pragma unroll 2
    for(int k4=0;k4<16;k4++){
        float v4[8][4];
        #pragma unroll
        for(int i=0;i<8;i++)
            *(float4*)v4[i] = *(const float4*)&xs[(tg+4*i)*64 + ((k4*4) ^ xsw)];
        #pragma unroll
        for(int kk=0;kk<4;kk++){
            int k = k4*4 + kk;
            ulonglong2 p0 = *(const ulonglong2*)&g_ctrT[k*NC + cb];
            #pragma unroll
            for(int i=0;i<8;i++){
                u64 xv = dupf(v4[i][kk]);
                ffma2(acc[i][0], xv, p0.x);
                ffma2(acc[i][1], xv, p0.y);
            }
        }
    }
    // key = c2b - 2*(x.c), write to ds
    {
        ulonglong2 q0 = *(const ulonglong2*)&g_c2[cb];
        u64 m2 = dupf(-2.0f);
        #pragma unroll
        for(int i=0;i<8;i++){
            int r = tg + 4*i;
            *(ulonglong2*)&ds[r*NC + cb] =
                make_ulonglong2(ffma2v(acc[i][0], m2, q0.x),
                                ffma2v(acc[i][1], m2, q0.y));
        }
    }
    __syncthreads();

    // ---- selection: warp w handles tokens tA = 2w, tB = 2w+1 ----
    int tA = w*2, tB = w*2+1;
    u64* PbA = Pb + (size_t)w*1024;
    u64* PbB = PbA + 512;

    u64 hA, hB;
    {   // token A: load (stride-32, conflict-free), pack, sort, spill
        u64 P[16];
        #pragma unroll
        for(int i=0;i<16;i++){
            float v = ds[tA*NC + lane + 32*i];
            P[i] = ((u64)__float_as_uint(v) << 32) | (u32)(i*32 + lane);
        }
        BITONIC16(P);
        #pragma unroll
        for(int i=0;i<16;i++) PbA[i*32 + lane] = P[i];
        hA = P[0];
    }
    {   // token B
        u64 P[16];
        #pragma unroll
        for(int i=0;i<16;i++){
            float v = ds[tB*NC + lane + 32*i];
            P[i] = ((u64)__float_as_uint(v) << 32) | (u32)(i*32 + lane);
        }
        BITONIC16(P);
        #pragma unroll
        for(int i=0;i<16;i++) PbB[i*32 + lane] = P[i];
        hB = P[0];
    }

    int idxA = 1, idxB = 1;
    u32 selkA = 0, selcA = 0, selkB = 0, selcB = 0;
    #pragma unroll
    for(int j=0;j<16;j++){
        u32 kA = (u32)(hA >> 32), kB = (u32)(hB >> 32);
        u32 mA = __reduce_min_sync(0xffffffffu, kA);
        u32 mB = __reduce_min_sync(0xffffffffu, kB);
        unsigned bA = __ballot_sync(0xffffffffu, kA == mA);
        unsigned bB = __ballot_sync(0xffffffffu, kB == mB);
        int wA = __ffs(bA) - 1, wB = __ffs(bB) - 1;
        u32 cA = __shfl_sync(0xffffffffu, (u32)hA, wA);
        u32 cB = __shfl_sync(0xffffffffu, (u32)hB, wB);
        if(lane == j){ selkA = mA; selcA = cA; selkB = mB; selcB = cB; }
        if(lane == wA){
            u64 nh = ~0ull;
            if(idxA < 16) nh = PbA[idxA*32 + lane];
            hA = nh; idxA++;
        }
        if(lane == wB){
            u64 nh = ~0ull;
            if(idxB < 16) nh = PbB[idxB*32 + lane];
            hB = nh; idxB++;
        }
    }

    // softmax over the 16 selections (lane j holds j-th smallest key)
    if(lane < 16){
        float dA = __uint_as_float(selkA);
        float dB = __uint_as_float(selkB);
        float mA0 = __shfl_sync(0x0000ffffu, dA, 0);
        float mB0 = __shfl_sync(0x0000ffffu, dB, 0);
        float eA = expf(mA0 - dA);
        float eB = expf(mB0 - dB);
        float sA = eA, sB = eB;
        #pragma unroll
        for(int o=8;o>=1;o>>=1){
            sA += __shfl_xor_sync(0x0000ffffu, sA, o);
            sB += __shfl_xor_sync(0x0000ffffu, sB, o);
        }
        int gtA = ttile + tA, gtB = ttile + tB;
        g_scores[gtA*16 + lane] = eA / sA;
        g_idx[gtA*16 + lane]    = (int)selcA;
        g_scores[gtB*16 + lane] = eB / sB;
        g_idx[gtB*16 + lane]    = (int)selcB;
        atomicAdd(&g_cnt[selcA], 1);
        atomicAdd(&g_cnt[selcB], 1);
    }
}

// ---------------- K2: fused scan (block 0) + scatter (all 512 blocks) ----------
__global__ __launch_bounds__(512) void k_ss(){
    __shared__ int wsum[16];
    int tid = threadIdx.x;

    if(blockIdx.x == 0){
        int c = tid, lane = c & 31, w = c >> 5;
        int cn = g_cnt[c];
        int s = cn;
        #pragma unroll
        for(int o=1;o<32;o<<=1){ int v=__shfl_up_sync(0xffffffffu,s,o); if(lane>=o) s+=v; }
        if(lane==31) wsum[w] = s;
        __syncthreads();
        if(w==0){
            int t = (lane<16) ? wsum[lane] : 0;
            #pragma unroll
            for(int o=1;o<16;o<<=1){ int v=__shfl_up_sync(0xffffffffu,t,o); if(lane>=o) t+=v; }
            if(lane<16) wsum[lane] = t;
        }
        __syncthreads();
        int inc = s + ((w>0) ? wsum[w-1] : 0);
        g_off[c] = inc - cn;
        g_cursor[c] = inc - cn;

        int t = (cn + 127) >> 7;
        __syncthreads();
        int s2 = t;
        #pragma unroll
        for(int o=1;o<32;o<<=1){ int v=__shfl_up_sync(0xffffffffu,s2,o); if(lane>=o) s2+=v; }
        if(lane==31) wsum[w] = s2;
        __syncthreads();
        if(w==0){
            int tt = (lane<16) ? wsum[lane] : 0;
            #pragma unroll
            for(int o=1;o<16;o<<=1){ int v=__shfl_up_sync(0xffffffffu,tt,o); if(lane>=o) tt+=v; }
            if(lane<16) wsum[lane] = tt;
        }
        __syncthreads();
        int tinc = s2 + ((w>0) ? wsum[w-1] : 0);
        int tb = tinc - t;
        for(int i=0;i<t;i++){
            g_tiles[2*(tb+i)]   = c;
            g_tiles[2*(tb+i)+1] = i << 7;
        }
        if(c == 511) g_ntiles = tinc;
        __threadfence();
        __syncthreads();
        if(tid == 0) *((volatile int*)&g_flag) = 1;
    } else {
        if(tid == 0){ while(*((volatile int*)&g_flag) == 0){ } }
        __syncthreads();
    }

    int a = blockIdx.x*512 + tid;          // (token<<4)|j
    int c = g_idx[a];
    float s = g_scores[a];
    int pos = atomicAdd(&g_cursor[c], 1);
    g_tok[pos]   = a >> 4;
    g_ascore[pos]= s;
    g_dslot[pos] = a;
}

// ---------------- K3: grouped GEMM per (center, 128-row tile) ------------------
// 256 thr, thread tile 4 rows x 8 cols (split og*4 / og*4+32).
// Warp w owns rows [16w, 16w+16): whole-warp skip when 16w >= m.
__global__ __launch_bounds__(256,3) void k_gemm(const float* __restrict__ x,
                                                const float* __restrict__ Wv,
                                                const float* __restrict__ Ov){
    __shared__ float ws[DIN*DOUT];   // ws[k*64 + p] (row-major copy of Wv[c])
    __shared__ float xs[128*DIN];    // xs[r*64 + (k ^ 8*((r>>2)&3))]
    __shared__ int s_tile;
    int nt = g_ntiles;
    int tid = threadIdx.x;
    int og = tid & 7, tg = tid >> 3;     // tg 0..31
    int w  = tid >> 5;
    int xsw = (tg & 3) * 8;              // rows tg*4..tg*4+3 share (r>>2)&3 == tg&3
    const float4* x4 = (const float4*)x;

    while(true){
        __syncthreads();             // smem reuse + s_tile protection
        if(tid == 0) s_tile = atomicAdd(&g_work, 1);
        __syncthreads();
        int tile = s_tile;
        if(tile >= nt) break;

        int c      = g_tiles[2*tile];
        int rstart = g_tiles[2*tile+1];
        int base   = g_off[c] + rstart;
        int m      = g_cnt[c] - rstart; if(m > 128) m = 128;

        const float4* wv4 = (const float4*)(Wv + (size_t)c*4096);
        float4* ws4 = (float4*)ws;
        #pragma unroll
        for(int f=0; f<4; f++) ws4[tid + 256*f] = wv4[tid + 256*f];

        #pragma unroll
        for(int it=0; it<8; it++){
            int idx2 = tid + 256*it;
            int rr = idx2 >> 4, seg = idx2 & 15;
            if(rr < m){
                float4 v = x4[g_tok[base+rr]*16 + seg];
                *(float4*)&xs[rr*64 + ((seg*4) ^ (((rr>>2)&3)*8))] = v;
            }
        }
        __syncthreads();

        if(16*w < m){                   // warp-uniform: skip padded rows
            u64 acc[4][4];
            #pragma unroll
            for(int i=0;i<4;i++){ acc[i][0]=0; acc[i][1]=0; acc[i][2]=0; acc[i][3]=0; }

            #pragma unroll 4
            for(int k4=0;k4<16;k4++){
                float v4[4][4];
                #pragma unroll
                for(int i=0;i<4;i++)
                    *(float4*)v4[i] = *(const float4*)&xs[(tg*4+i)*64 + ((k4*4) ^ xsw)];
                #pragma unroll
                for(int kk=0;kk<4;kk++){
                    int k = k4*4 + kk;
                    ulonglong2 p0 = *(const ulonglong2*)&ws[k*64 + og*4];
                    ulonglong2 p1 = *(const ulonglong2*)&ws[k*64 + og*4 + 32];
                    #pragma unroll
                    for(int i=0;i<4;i++){
                        u64 xv = dupf(v4[i][kk]);
                        ffma2(acc[i][0], xv, p0.x);
                        ffma2(acc[i][1], xv, p0.y);
                        ffma2(acc[i][2], xv, p1.x);
                        ffma2(acc[i][3], xv, p1.y);
                    }
                }
            }
            ulonglong2 q0 = *(const ulonglong2*)&Ov[(size_t)c*64 + og*4];
            ulonglong2 q1 = *(const ulonglong2*)&Ov[(size_t)c*64 + og*4 + 32];
            #pragma unroll
            for(int i=0;i<4;i++){
                int r = tg*4 + i;
                if(r < m){
                    int slot = g_dslot[base + r];
                    u64 sv = dupf(g_ascore[base + r]);
                    ulonglong2* d0 = (ulonglong2*)&g_part[(size_t)slot*64 + og*4];
                    ulonglong2* d1 = (ulonglong2*)&g_part[(size_t)slot*64 + og*4 + 32];
                    *d0 = make_ulonglong2(fmul2(fadd2(acc[i][0], q0.x), sv),
                                          fmul2(fadd2(acc[i][1], q0.y), sv));
                    *d1 = make_ulonglong2(fmul2(fadd2(acc[i][2], q1.x), sv),
                                          fmul2(fadd2(acc[i][3], q1.y), sv));
                }
            }
        }
    }
}

// ---------------- K4: streamed reduce of 16 contiguous partials per token ------
__global__ __launch_bounds__(256) void k_reduce(float* __restrict__ out){
    int t  = blockIdx.x*16 + (threadIdx.x >> 4);
    int c4 = threadIdx.x & 15;
    const float4* p = (const float4*)(g_part + (size_t)t*16*64) + c4;
    float4 acc = make_float4(0.f,0.f,0.f,0.f);
    #pragma unroll
    for(int j=0;j<16;j++){
        float4 v = p[j*16];
        acc.x += v.x; acc.y += v.y; acc.z += v.z; acc.w += v.w;
    }
    ((float4*)out)[t*16 + c4] = acc;
}

// ---------------- launch -------------------------------------------------------
extern "C" void kernel_launch(void* const* d_in, const int* in_sizes, int n_in,
                              void* d_out, int out_size){
    const float* x    = (const float*)d_in[0];
    const float* ctrs = (const float*)d_in[1];
    const float* Wv   = (const float*)d_in[2];
    const float* Ov   = (const float*)d_in[3];
    float* out = (float*)d_out;

    const int FUSED_SMEM = (32*64 + 32*512)*4 + 16*2*512*8;   // 200 KB
    cudaFuncSetAttribute(k_fused, cudaFuncAttributeMaxDynamicSharedMemorySize,
                         FUSED_SMEM);

    k_prep_t<<<128, 256>>>(ctrs);
    k_prep_c<<<2, 256>>>(ctrs);
    k_prep_z<<<2, 256>>>();
    k_fused <<<512, 512, FUSED_SMEM>>>(x);   // launch #4 -> ncu capture target
    k_ss    <<<512, 512>>>();
    k_gemm  <<<444, 256>>>(x, Wv, Ov);
    k_reduce<<<1024, 256>>>(out);
}

// round 10
// speedup vs baseline: 1.0789x; 1.0122x over previous
#include <cuda_runtime.h>
#include <cstdint>

#define NTOK 16384
#define DIN 64
#define DOUT 64
#define NC 512
#define KSEL 16
#define NASSIGN (NTOK*KSEL)

typedef unsigned long long u64;
typedef unsigned int u32;

// ---------------- scratch (device globals: no allocation allowed) -------------
__device__ float g_ctrT[DIN*NC];        // centers transposed [k][c]
__device__ float g_scores[NASSIGN];     // softmax scores per (token, j)
__device__ int   g_idx[NASSIGN];        // selected center per (token, j)
__device__ int   g_cnt[NC];
__device__ int   g_off[NC];
__device__ int   g_cursor[NC];
__device__ int   g_tok[NASSIGN];        // bucket -> token id
__device__ float g_ascore[NASSIGN];     // bucket -> score
__device__ int   g_dslot[NASSIGN];      // bucket -> (token*16+j) destination slot
__device__ float g_part[(size_t)NASSIGN*DOUT]; // 67 MB partials, slot-addressed
__device__ float g_c2[NC];              // ||c||^2 + 1024 bias
__device__ int   g_tiles[8192];         // (center, rowStart) pairs
__device__ int   g_ntiles;
__device__ int   g_work;                // dynamic tile cursor for k_gemm
__device__ int   g_flag;                // scan-done flag for k_ss

// ---------------- packed f32x2 helpers ----------------------------------------
__device__ __forceinline__ u64 dupf(float x){
    u64 r; asm("mov.b64 %0, {%1, %1};" : "=l"(r) : "f"(x)); return r;
}
__device__ __forceinline__ void ffma2(u64 &d, u64 a, u64 b){
    asm("fma.rn.f32x2 %0, %1, %2, %0;" : "+l"(d) : "l"(a), "l"(b));
}
__device__ __forceinline__ u64 ffma2v(u64 a, u64 b, u64 c){
    u64 d; asm("fma.rn.f32x2 %0, %1, %2, %3;" : "=l"(d) : "l"(a), "l"(b), "l"(c)); return d;
}
__device__ __forceinline__ u64 fadd2(u64 a, u64 b){
    u64 r; asm("add.rn.f32x2 %0, %1, %2;" : "=l"(r) : "l"(a), "l"(b)); return r;
}
__device__ __forceinline__ u64 fmul2(u64 a, u64 b){
    u64 r; asm("mul.rn.f32x2 %0, %1, %2;" : "=l"(r) : "l"(a), "l"(b)); return r;
}

// bitonic sort 16 u64 ascending, fully unrolled, register-resident
#define BITONIC16(P) do{ \
    _Pragma("unroll") \
    for(int k_=2;k_<=16;k_<<=1){ \
        _Pragma("unroll") \
        for(int j_=k_>>1;j_>0;j_>>=1){ \
            _Pragma("unroll") \
            for(int i_=0;i_<16;i_++){ \
                int l_=i_^j_; \
                if(l_>i_){ \
                    bool up_=((i_&k_)==0); \
                    u64 a_=P[i_], b_=P[l_]; \
                    bool sw_= up_ ? (a_>b_) : (a_<b_); \
                    if(sw_){ P[i_]=b_; P[l_]=a_; } \
                } \
            } \
        } \
    } }while(0)

// ---------------- K0a: transpose centers ---------------------------------------
__global__ void k_prep_t(const float* __restrict__ ctrs){
    int e = blockIdx.x*256 + threadIdx.x;   // 32768 elements
    int k = e >> 9, c = e & 511;
    g_ctrT[k*NC + c] = ctrs[c*DIN + k];
}

// ---------------- K0b: c2 (+bias) ----------------------------------------------
__global__ void k_prep_c(const float* __restrict__ ctrs){
    int c = blockIdx.x*256 + threadIdx.x;   // 512 centers
    const float4* c4 = (const float4*)ctrs;
    float s = 1024.0f;  // bias keeps keys > 0; cancels in softmax
    #pragma unroll
    for(int seg=0; seg<16; seg++){
        float4 v = c4[c*16 + seg];
        s += v.x*v.x + v.y*v.y + v.z*v.z + v.w*v.w;
    }
    g_c2[c] = s;
}

// ---------------- K0c: zero counters -------------------------------------------
__global__ void k_prep_z(){
    int c = blockIdx.x*256 + threadIdx.x;
    g_cnt[c] = 0;
    if(c == 0){ g_work = 0; g_flag = 0; }
}

// ---------------- per-token branchless top-16 + softmax ------------------------
// candidates sorted per-lane in registers; pop = predicated register shift.
__device__ __forceinline__ void select16(const float* ds, int t, int lane,
                                         int gt){
    u64 P[16];
    #pragma unroll
    for(int i=0;i<16;i++){
        float v = ds[t*NC + lane + 32*i];
        P[i] = ((u64)__float_as_uint(v) << 32) | (u32)(i*32 + lane);
    }
    BITONIC16(P);

    u32 selk = 0, selc = 0;
    #pragma unroll
    for(int j=0;j<16;j++){
        u32 k = (u32)(P[0] >> 32);
        u32 m = __reduce_min_sync(0xffffffffu, k);
        unsigned b = __ballot_sync(0xffffffffu, k == m);
        int wsel = __ffs(b) - 1;
        u32 c = __shfl_sync(0xffffffffu, (u32)P[0], wsel);
        if(lane == j){ selk = m; selc = c; }
        bool take = (lane == wsel);
        #pragma unroll
        for(int i=0;i<15;i++) P[i] = take ? P[i+1] : P[i];
        P[15] = take ? ~0ull : P[15];
    }

    if(lane < 16){
        float d = __uint_as_float(selk);
        float m0 = __shfl_sync(0x0000ffffu, d, 0);
        float e = expf(m0 - d);
        float s = e;
        #pragma unroll
        for(int o=8;o>=1;o>>=1) s += __shfl_xor_sync(0x0000ffffu, s, o);
        g_scores[gt*16 + lane] = e / s;
        g_idx[gt*16 + lane]    = (int)selc;
        atomicAdd(&g_cnt[selc], 1);
    }
}

// ---------------- K1: fused distance GEMM + branchless top-16 + softmax --------
// block: 32 tokens x 512 centers.  512 thr = 16 warps; warp w owns 32 centers.
// smem 72KB -> L1 carveout ~156KB keeps g_ctrT (128KB) L1-resident.
__global__ __launch_bounds__(512,1) void k_fused(const float* __restrict__ x){
    extern __shared__ char smraw[];
    float* xs  = (float*)smraw;            // 32*64    swizzled x tile (8KB)
    float* ds  = xs + 32*64;               // 32*512   distance keys   (64KB)

    int tid = threadIdx.x;
    int ttile = blockIdx.x*32;

    // load x tile (32 tokens), swizzled xs[r*64 + (k ^ 8*(r&3))]
    const float4* x4 = (const float4*)x;
    {
        int rr = tid >> 4, seg = tid & 15;
        float4 v = x4[(ttile+rr)*16 + seg];
        *(float4*)&xs[rr*64 + ((seg*4) ^ ((rr&3)*8))] = v;
    }
    __syncthreads();

    int w  = tid >> 5, lane = tid & 31;
    int og = lane & 7, tg = lane >> 3;     // tg in 0..3
    int cb = w*32 + og*4;                  // this thread's 4 centers
    int xsw = tg*8;

    u64 acc[8][2];
    #pragma unroll
    for(int i=0;i<8;i++){ acc[i][0]=0; acc[i][1]=0; }

    #pragma unroll 2
    for(int k4=0;k4<16;k4++){
        float v4[8][4];
        #pragma unroll
        for(int i=0;i<8;i++)
            *(float4*)v4[i] = *(const float4*)&xs[(tg+4*i)*64 + ((k4*4) ^ xsw)];
        #pragma unroll
        for(int kk=0;kk<4;kk++){
            int k = k4*4 + kk;
            ulonglong2 p0 = *(const ulonglong2*)&g_ctrT[k*NC + cb];
            #pragma unroll
            for(int i=0;i<8;i++){
                u64 xv = dupf(v4[i][kk]);
                ffma2(acc[i][0], xv, p0.x);
                ffma2(acc[i][1], xv, p0.y);
            }
        }
    }
    // key = c2b - 2*(x.c), write to ds
    {
        ulonglong2 q0 = *(const ulonglong2*)&g_c2[cb];
        u64 m2 = dupf(-2.0f);
        #pragma unroll
        for(int i=0;i<8;i++){
            int r = tg + 4*i;
            *(ulonglong2*)&ds[r*NC + cb] =
                make_ulonglong2(ffma2v(acc[i][0], m2, q0.x),
                                ffma2v(acc[i][1], m2, q0.y));
        }
    }
    __syncthreads();

    // selection: warp w handles tokens 2w, 2w+1 (sequential: low reg pressure)
    select16(ds, w*2,     lane, ttile + w*2);
    select16(ds, w*2 + 1, lane, ttile + w*2 + 1);
}

// ---------------- K2: fused scan (block 0) + scatter (all 512 blocks) ----------
__global__ __launch_bounds__(512) void k_ss(){
    __shared__ int wsum[16];
    int tid = threadIdx.x;

    if(blockIdx.x == 0){
        int c = tid, lane = c & 31, w = c >> 5;
        int cn = g_cnt[c];
        int s = cn;
        #pragma unroll
        for(int o=1;o<32;o<<=1){ int v=__shfl_up_sync(0xffffffffu,s,o); if(lane>=o) s+=v; }
        if(lane==31) wsum[w] = s;
        __syncthreads();
        if(w==0){
            int t = (lane<16) ? wsum[lane] : 0;
            #pragma unroll
            for(int o=1;o<16;o<<=1){ int v=__shfl_up_sync(0xffffffffu,t,o); if(lane>=o) t+=v; }
            if(lane<16) wsum[lane] = t;
        }
        __syncthreads();
        int inc = s + ((w>0) ? wsum[w-1] : 0);
        g_off[c] = inc - cn;
        g_cursor[c] = inc - cn;

        int t = (cn + 127) >> 7;
        __syncthreads();
        int s2 = t;
        #pragma unroll
        for(int o=1;o<32;o<<=1){ int v=__shfl_up_sync(0xffffffffu,s2,o); if(lane>=o) s2+=v; }
        if(lane==31) wsum[w] = s2;
        __syncthreads();
        if(w==0){
            int tt = (lane<16) ? wsum[lane] : 0;
            #pragma unroll
            for(int o=1;o<16;o<<=1){ int v=__shfl_up_sync(0xffffffffu,tt,o); if(lane>=o) tt+=v; }
            if(lane<16) wsum[lane] = tt;
        }
        __syncthreads();
        int tinc = s2 + ((w>0) ? wsum[w-1] : 0);
        int tb = tinc - t;
        for(int i=0;i<t;i++){
            g_tiles[2*(tb+i)]   = c;
            g_tiles[2*(tb+i)+1] = i << 7;
        }
        if(c == 511) g_ntiles = tinc;
        __threadfence();
        __syncthreads();
        if(tid == 0) *((volatile int*)&g_flag) = 1;
    } else {
        if(tid == 0){ while(*((volatile int*)&g_flag) == 0){ } }
        __syncthreads();
    }

    int a = blockIdx.x*512 + tid;          // (token<<4)|j
    int c = g_idx[a];
    float s = g_scores[a];
    int pos = atomicAdd(&g_cursor[c], 1);
    g_tok[pos]   = a >> 4;
    g_ascore[pos]= s;
    g_dslot[pos] = a;
}

// ---------------- K3: grouped GEMM per (center, 128-row tile) ------------------
// 256 thr, thread tile 4 rows x 8 cols (split og*4 / og*4+32).
// Warp w owns rows [16w, 16w+16): whole-warp skip when 16w >= m.
__global__ __launch_bounds__(256,3) void k_gemm(const float* __restrict__ x,
                                                const float* __restrict__ Wv,
                                                const float* __restrict__ Ov){
    __shared__ float ws[DIN*DOUT];   // ws[k*64 + p] (row-major copy of Wv[c])
    __shared__ float xs[128*DIN];    // xs[r*64 + (k ^ 8*((r>>2)&3))]
    __shared__ int s_tile;
    int nt = g_ntiles;
    int tid = threadIdx.x;
    int og = tid & 7, tg = tid >> 3;     // tg 0..31
    int w  = tid >> 5;
    int xsw = (tg & 3) * 8;              // rows tg*4..tg*4+3 share (r>>2)&3 == tg&3
    const float4* x4 = (const float4*)x;

    while(true){
        __syncthreads();             // smem reuse + s_tile protection
        if(tid == 0) s_tile = atomicAdd(&g_work, 1);
        __syncthreads();
        int tile = s_tile;
        if(tile >= nt) break;

        int c      = g_tiles[2*tile];
        int rstart = g_tiles[2*tile+1];
        int base   = g_off[c] + rstart;
        int m      = g_cnt[c] - rstart; if(m > 128) m = 128;

        const float4* wv4 = (const float4*)(Wv + (size_t)c*4096);
        float4* ws4 = (float4*)ws;
        #pragma unroll
        for(int f=0; f<4; f++) ws4[tid + 256*f] = wv4[tid + 256*f];

        #pragma unroll
        for(int it=0; it<8; it++){
            int idx2 = tid + 256*it;
            int rr = idx2 >> 4, seg = idx2 & 15;
            if(rr < m){
                float4 v = x4[g_tok[base+rr]*16 + seg];
                *(float4*)&xs[rr*64 + ((seg*4) ^ (((rr>>2)&3)*8))] = v;
            }
        }
        __syncthreads();

        if(16*w < m){                   // warp-uniform: skip padded rows
            u64 acc[4][4];
            #pragma unroll
            for(int i=0;i<4;i++){ acc[i][0]=0; acc[i][1]=0; acc[i][2]=0; acc[i][3]=0; }

            #pragma unroll 4
            for(int k4=0;k4<16;k4++){
                float v4[4][4];
                #pragma unroll
                for(int i=0;i<4;i++)
                    *(float4*)v4[i] = *(const float4*)&xs[(tg*4+i)*64 + ((k4*4) ^ xsw)];
                #pragma unroll
                for(int kk=0;kk<4;kk++){
                    int k = k4*4 + kk;
                    ulonglong2 p0 = *(const ulonglong2*)&ws[k*64 + og*4];
                    ulonglong2 p1 = *(const ulonglong2*)&ws[k*64 + og*4 + 32];
                    #pragma unroll
                    for(int i=0;i<4;i++){
                        u64 xv = dupf(v4[i][kk]);
                        ffma2(acc[i][0], xv, p0.x);
                        ffma2(acc[i][1], xv, p0.y);
                        ffma2(acc[i][2], xv, p1.x);
                        ffma2(acc[i][3], xv, p1.y);
                    }
                }
            }
            ulonglong2 q0 = *(const ulonglong2*)&Ov[(size_t)c*64 + og*4];
            ulonglong2 q1 = *(const ulonglong2*)&Ov[(size_t)c*64 + og*4 + 32];
            #pragma unroll
            for(int i=0;i<4;i++){
                int r = tg*4 + i;
                if(r < m){
                    int slot = g_dslot[base + r];
                    u64 sv = dupf(g_ascore[base + r]);
                    ulonglong2* d0 = (ulonglong2*)&g_part[(size_t)slot*64 + og*4];
                    ulonglong2* d1 = (ulonglong2*)&g_part[(size_t)slot*64 + og*4 + 32];
                    *d0 = make_ulonglong2(fmul2(fadd2(acc[i][0], q0.x), sv),
                                          fmul2(fadd2(acc[i][1], q0.y), sv));
                    *d1 = make_ulonglong2(fmul2(fadd2(acc[i][2], q1.x), sv),
                                          fmul2(fadd2(acc[i][3], q1.y), sv));
                }
            }
        }
    }
}

// ---------------- K4: streamed reduce of 16 contiguous partials per token ------
__global__ __launch_bounds__(256) void k_reduce(float* __restrict__ out){
    int t  = blockIdx.x*16 + (threadIdx.x >> 4);
    int c4 = threadIdx.x & 15;
    const float4* p = (const float4*)(g_part + (size_t)t*16*64) + c4;
    float4 acc = make_float4(0.f,0.f,0.f,0.f);
    #pragma unroll
    for(int j=0;j<16;j++){
        float4 v = p[j*16];
        acc.x += v.x; acc.y += v.y; acc.z += v.z; acc.w += v.w;
    }
    ((float4*)out)[t*16 + c4] = acc;
}

// ---------------- launch -------------------------------------------------------
extern "C" void kernel_launch(void* const* d_in, const int* in_sizes, int n_in,
                              void* d_out, int out_size){
    const float* x    = (const float*)d_in[0];
    const float* ctrs = (const float*)d_in[1];
    const float* Wv   = (const float*)d_in[2];
    const float* Ov   = (const float*)d_in[3];
    float* out = (float*)d_out;

    const int FUSED_SMEM = (32*64 + 32*512)*4;   // 72 KB
    cudaFuncSetAttribute(k_fused, cudaFuncAttributeMaxDynamicSharedMemorySize,
                         FUSED_SMEM);

    k_prep_t<<<128, 256>>>(ctrs);
    k_prep_c<<<2, 256>>>(ctrs);
    k_prep_z<<<2, 256>>>();
    k_fused <<<512, 512, FUSED_SMEM>>>(x);   // launch #4 -> ncu capture target
    k_ss    <<<512, 512>>>();
    k_gemm  <<<444, 256>>>(x, Wv, Ov);
    k_reduce<<<1024, 256>>>(out);
}

// round 11
// speedup vs baseline: 1.1771x; 1.0909x over previous
#include <cuda_runtime.h>
#include <cstdint>

#define NTOK 16384
#define DIN 64
#define DOUT 64
#define NC 512
#define KSEL 16
#define NASSIGN (NTOK*KSEL)

typedef unsigned long long u64;
typedef unsigned int u32;

// ---------------- scratch (device globals: no allocation allowed) -------------
__device__ float g_ctrT[DIN*NC];        // centers transposed [k][c]
__device__ float g_scores[NASSIGN];     // softmax scores per (token, j)
__device__ int   g_idx[NASSIGN];        // selected center per (token, j)
__device__ int   g_cnt[NC];
__device__ int   g_off[NC];
__device__ int   g_cursor[NC];
__device__ int   g_tok[NASSIGN];        // bucket -> token id
__device__ float g_ascore[NASSIGN];     // bucket -> score
__device__ int   g_dslot[NASSIGN];      // bucket -> (token*16+j) destination slot
__device__ float g_part[(size_t)NASSIGN*DOUT]; // 67 MB partials, slot-addressed
__device__ float g_c2[NC];              // ||c||^2 + 3072 bias
__device__ int   g_tiles[8192];         // (center, rowStart) pairs
__device__ int   g_ntiles;
__device__ int   g_work;                // dynamic tile cursor for k_gemm
__device__ int   g_flag;                // scan-done flag for k_ss

// ---------------- packed f32x2 helpers ----------------------------------------
__device__ __forceinline__ u64 dupf(float x){
    u64 r; asm("mov.b64 %0, {%1, %1};" : "=l"(r) : "f"(x)); return r;
}
__device__ __forceinline__ void ffma2(u64 &d, u64 a, u64 b){
    asm("fma.rn.f32x2 %0, %1, %2, %0;" : "+l"(d) : "l"(a), "l"(b));
}
__device__ __forceinline__ u64 ffma2v(u64 a, u64 b, u64 c){
    u64 d; asm("fma.rn.f32x2 %0, %1, %2, %3;" : "=l"(d) : "l"(a), "l"(b), "l"(c)); return d;
}
__device__ __forceinline__ u64 fadd2(u64 a, u64 b){
    u64 r; asm("add.rn.f32x2 %0, %1, %2;" : "=l"(r) : "l"(a), "l"(b)); return r;
}
__device__ __forceinline__ u64 fmul2(u64 a, u64 b){
    u64 r; asm("mul.rn.f32x2 %0, %1, %2;" : "=l"(r) : "l"(a), "l"(b)); return r;
}

// bitonic sort of 16 u32 ascending: every CAS = 2 IMNMX (direction resolved
// at compile time), fully unrolled, register-resident.
#define BITONIC16U(P) do{ \
    _Pragma("unroll") \
    for(int k_=2;k_<=16;k_<<=1){ \
        _Pragma("unroll") \
        for(int j_=k_>>1;j_>0;j_>>=1){ \
            _Pragma("unroll") \
            for(int i_=0;i_<16;i_++){ \
                int l_=i_^j_; \
                if(l_>i_){ \
                    u32 a_=P[i_], b_=P[l_]; \
                    u32 lo_ = a_<b_?a_:b_, hi_ = a_<b_?b_:a_; \
                    if((i_&k_)==0){ P[i_]=lo_; P[l_]=hi_; } \
                    else          { P[i_]=hi_; P[l_]=lo_; } \
                } \
            } \
        } \
    } }while(0)

// ---------------- K0a: transpose centers ---------------------------------------
__global__ void k_prep_t(const float* __restrict__ ctrs){
    int e = blockIdx.x*256 + threadIdx.x;   // 32768 elements
    int k = e >> 9, c = e & 511;
    g_ctrT[k*NC + c] = ctrs[c*DIN + k];
}

// ---------------- K0b: c2 (+bias) ----------------------------------------------
// bias 3072 puts every key = 3072 + ||c||^2 - 2 x.c inside the [2048,4096)
// float binade (needs >40 sigma to escape), so the 23 mantissa bits alone give
// the exact ordering -> u32 packed selection. Bias cancels in softmax.
__global__ void k_prep_c(const float* __restrict__ ctrs){
    int c = blockIdx.x*256 + threadIdx.x;   // 512 centers
    const float4* c4 = (const float4*)ctrs;
    float s = 3072.0f;
    #pragma unroll
    for(int seg=0; seg<16; seg++){
        float4 v = c4[c*16 + seg];
        s += v.x*v.x + v.y*v.y + v.z*v.z + v.w*v.w;
    }
    g_c2[c] = s;
}

// ---------------- K0c: zero counters -------------------------------------------
__global__ void k_prep_z(){
    int c = blockIdx.x*256 + threadIdx.x;
    g_cnt[c] = 0;
    if(c == 0){ g_work = 0; g_flag = 0; }
}

// ---------------- per-token branchless top-16 + softmax (u32 packed) -----------
// pack = (float_bits << 9) | center (unique, exact order within one binade).
__device__ __forceinline__ void select16(const float* ds, int t, int lane,
                                         int gt){
    u32 P[16];
    #pragma unroll
    for(int i=0;i<16;i++){
        float v = ds[t*NC + lane + 32*i];
        P[i] = (__float_as_uint(v) << 9) | (u32)(i*32 + lane);
    }
    BITONIC16U(P);

    u32 sel = 0;
    #pragma unroll
    for(int j=0;j<16;j++){
        u32 m = __reduce_min_sync(0xffffffffu, P[0]);
        if(lane == j) sel = m;
        bool take = (P[0] == m);      // packed values unique -> exactly one lane
        #pragma unroll
        for(int i=0;i<15;i++) P[i] = take ? P[i+1] : P[i];
        P[15] = take ? 0xFFFFFFFFu : P[15];
    }

    if(lane < 16){
        u32 c = sel & 511u;
        float d = __uint_as_float(0x45000000u | (sel >> 9));  // exact key
        float m0 = __shfl_sync(0x0000ffffu, d, 0);
        float e = expf(m0 - d);
        float s = e;
        #pragma unroll
        for(int o=8;o>=1;o>>=1) s += __shfl_xor_sync(0x0000ffffu, s, o);
        g_scores[gt*16 + lane] = e / s;
        g_idx[gt*16 + lane]    = (int)c;
        atomicAdd(&g_cnt[c], 1);
    }
}

// ---------------- K1: fused distance GEMM + branchless top-16 + softmax --------
// block: 32 tokens x 512 centers.  512 thr = 16 warps; warp w owns 32 centers.
// smem 72KB -> L1 carveout ~156KB keeps g_ctrT (128KB) L1-resident.
__global__ __launch_bounds__(512,1) void k_fused(const float* __restrict__ x){
    extern __shared__ char smraw[];
    float* xs  = (float*)smraw;            // 32*64    swizzled x tile (8KB)
    float* ds  = xs + 32*64;               // 32*512   distance keys   (64KB)

    int tid = threadIdx.x;
    int ttile = blockIdx.x*32;

    // load x tile (32 tokens), swizzled xs[r*64 + (k ^ 8*(r&3))]
    const float4* x4 = (const float4*)x;
    {
        int rr = tid >> 4, seg = tid & 15;
        float4 v = x4[(ttile+rr)*16 + seg];
        *(float4*)&xs[rr*64 + ((seg*4) ^ ((rr&3)*8))] = v;
    }
    __syncthreads();

    int w  = tid >> 5, lane = tid & 31;
    int og = lane & 7, tg = lane >> 3;     // tg in 0..3
    int cb = w*32 + og*4;                  // this thread's 4 centers
    int xsw = tg*8;

    u64 acc[8][2];
    #pragma unroll
    for(int i=0;i<8;i++){ acc[i][0]=0; acc[i][1]=0; }

    #pragma unroll 2
    for(int k4=0;k4<16;k4++){
        float v4[8][4];
        #pragma unroll
        for(int i=0;i<8;i++)
            *(float4*)v4[i] = *(const float4*)&xs[(tg+4*i)*64 + ((k4*4) ^ xsw)];
        #pragma unroll
        for(int kk=0;kk<4;kk++){
            int k = k4*4 + kk;
            ulonglong2 p0 = *(const ulonglong2*)&g_ctrT[k*NC + cb];
            #pragma unroll
            for(int i=0;i<8;i++){
                u64 xv = dupf(v4[i][kk]);
                ffma2(acc[i][0], xv, p0.x);
                ffma2(acc[i][1], xv, p0.y);
            }
        }
    }
    // key = c2b - 2*(x.c), write to ds
    {
        ulonglong2 q0 = *(const ulonglong2*)&g_c2[cb];
        u64 m2 = dupf(-2.0f);
        #pragma unroll
        for(int i=0;i<8;i++){
            int r = tg + 4*i;
            *(ulonglong2*)&ds[r*NC + cb] =
                make_ulonglong2(ffma2v(acc[i][0], m2, q0.x),
                                ffma2v(acc[i][1], m2, q0.y));
        }
    }
    __syncthreads();

    // selection: warp w handles tokens 2w, 2w+1
    select16(ds, w*2,     lane, ttile + w*2);
    select16(ds, w*2 + 1, lane, ttile + w*2 + 1);
}

// ---------------- K2: fused scan (block 0) + scatter (all 512 blocks) ----------
__global__ __launch_bounds__(512) void k_ss(){
    __shared__ int wsum[16];
    int tid = threadIdx.x;

    if(blockIdx.x == 0){
        int c = tid, lane = c & 31, w = c >> 5;
        int cn = g_cnt[c];
        int s = cn;
        #pragma unroll
        for(int o=1;o<32;o<<=1){ int v=__shfl_up_sync(0xffffffffu,s,o); if(lane>=o) s+=v; }
        if(lane==31) wsum[w] = s;
        __syncthreads();
        if(w==0){
            int t = (lane<16) ? wsum[lane] : 0;
            #pragma unroll
            for(int o=1;o<16;o<<=1){ int v=__shfl_up_sync(0xffffffffu,t,o); if(lane>=o) t+=v; }
            if(lane<16) wsum[lane] = t;
        }
        __syncthreads();
        int inc = s + ((w>0) ? wsum[w-1] : 0);
        g_off[c] = inc - cn;
        g_cursor[c] = inc - cn;

        int t = (cn + 127) >> 7;
        __syncthreads();
        int s2 = t;
        #pragma unroll
        for(int o=1;o<32;o<<=1){ int v=__shfl_up_sync(0xffffffffu,s2,o); if(lane>=o) s2+=v; }
        if(lane==31) wsum[w] = s2;
        __syncthreads();
        if(w==0){
            int tt = (lane<16) ? wsum[lane] : 0;
            #pragma unroll
            for(int o=1;o<16;o<<=1){ int v=__shfl_up_sync(0xffffffffu,tt,o); if(lane>=o) tt+=v; }
            if(lane<16) wsum[lane] = tt;
        }
        __syncthreads();
        int tinc = s2 + ((w>0) ? wsum[w-1] : 0);
        int tb = tinc - t;
        for(int i=0;i<t;i++){
            g_tiles[2*(tb+i)]   = c;
            g_tiles[2*(tb+i)+1] = i << 7;
        }
        if(c == 511) g_ntiles = tinc;
        __threadfence();
        __syncthreads();
        if(tid == 0) *((volatile int*)&g_flag) = 1;
    } else {
        if(tid == 0){ while(*((volatile int*)&g_flag) == 0){ } }
        __syncthreads();
    }

    int a = blockIdx.x*512 + tid;          // (token<<4)|j
    int c = g_idx[a];
    float s = g_scores[a];
    int pos = atomicAdd(&g_cursor[c], 1);
    g_tok[pos]   = a >> 4;
    g_ascore[pos]= s;
    g_dslot[pos] = a;
}

// ---------------- K3: grouped GEMM per (center, 128-row tile) ------------------
// 256 thr, thread tile 4 rows x 8 cols (split og*4 / og*4+32).
// Warp w owns rows [16w, 16w+16): whole-warp skip when 16w >= m.
__global__ __launch_bounds__(256,3) void k_gemm(const float* __restrict__ x,
                                                const float* __restrict__ Wv,
                                                const float* __restrict__ Ov){
    __shared__ float ws[DIN*DOUT];   // ws[k*64 + p] (row-major copy of Wv[c])
    __shared__ float xs[128*DIN];    // xs[r*64 + (k ^ 8*((r>>2)&3))]
    __shared__ int s_tile;
    int nt = g_ntiles;
    int tid = threadIdx.x;
    int og = tid & 7, tg = tid >> 3;     // tg 0..31
    int w  = tid >> 5;
    int xsw = (tg & 3) * 8;              // rows tg*4..tg*4+3 share (r>>2)&3 == tg&3
    const float4* x4 = (const float4*)x;

    while(true){
        __syncthreads();             // smem reuse + s_tile protection
        if(tid == 0) s_tile = atomicAdd(&g_work, 1);
        __syncthreads();
        int tile = s_tile;
        if(tile >= nt) break;

        int c      = g_tiles[2*tile];
        int rstart = g_tiles[2*tile+1];
        int base   = g_off[c] + rstart;
        int m      = g_cnt[c] - rstart; if(m > 128) m = 128;

        const float4* wv4 = (const float4*)(Wv + (size_t)c*4096);
        float4* ws4 = (float4*)ws;
        #pragma unroll
        for(int f=0; f<4; f++) ws4[tid + 256*f] = wv4[tid + 256*f];

        #pragma unroll
        for(int it=0; it<8; it++){
            int idx2 = tid + 256*it;
            int rr = idx2 >> 4, seg = idx2 & 15;
            if(rr < m){
                float4 v = x4[g_tok[base+rr]*16 + seg];
                *(float4*)&xs[rr*64 + ((seg*4) ^ (((rr>>2)&3)*8))] = v;
            }
        }
        __syncthreads();

        if(16*w < m){                   // warp-uniform: skip padded rows
            u64 acc[4][4];
            #pragma unroll
            for(int i=0;i<4;i++){ acc[i][0]=0; acc[i][1]=0; acc[i][2]=0; acc[i][3]=0; }

            #pragma unroll 4
            for(int k4=0;k4<16;k4++){
                float v4[4][4];
                #pragma unroll
                for(int i=0;i<4;i++)
                    *(float4*)v4[i] = *(const float4*)&xs[(tg*4+i)*64 + ((k4*4) ^ xsw)];
                #pragma unroll
                for(int kk=0;kk<4;kk++){
                    int k = k4*4 + kk;
                    ulonglong2 p0 = *(const ulonglong2*)&ws[k*64 + og*4];
                    ulonglong2 p1 = *(const ulonglong2*)&ws[k*64 + og*4 + 32];
                    #pragma unroll
                    for(int i=0;i<4;i++){
                        u64 xv = dupf(v4[i][kk]);
                        ffma2(acc[i][0], xv, p0.x);
                        ffma2(acc[i][1], xv, p0.y);
                        ffma2(acc[i][2], xv, p1.x);
                        ffma2(acc[i][3], xv, p1.y);
                    }
                }
            }
            ulonglong2 q0 = *(const ulonglong2*)&Ov[(size_t)c*64 + og*4];
            ulonglong2 q1 = *(const ulonglong2*)&Ov[(size_t)c*64 + og*4 + 32];
            #pragma unroll
            for(int i=0;i<4;i++){
                int r = tg*4 + i;
                if(r < m){
                    int slot = g_dslot[base + r];
                    u64 sv = dupf(g_ascore[base + r]);
                    ulonglong2* d0 = (ulonglong2*)&g_part[(size_t)slot*64 + og*4];
                    ulonglong2* d1 = (ulonglong2*)&g_part[(size_t)slot*64 + og*4 + 32];
                    *d0 = make_ulonglong2(fmul2(fadd2(acc[i][0], q0.x), sv),
                                          fmul2(fadd2(acc[i][1], q0.y), sv));
                    *d1 = make_ulonglong2(fmul2(fadd2(acc[i][2], q1.x), sv),
                                          fmul2(fadd2(acc[i][3], q1.y), sv));
                }
            }
        }
    }
}

// ---------------- K4: streamed reduce of 16 contiguous partials per token ------
__global__ __launch_bounds__(256) void k_reduce(float* __restrict__ out){
    int t  = blockIdx.x*16 + (threadIdx.x >> 4);
    int c4 = threadIdx.x & 15;
    const float4* p = (const float4*)(g_part + (size_t)t*16*64) + c4;
    float4 acc = make_float4(0.f,0.f,0.f,0.f);
    #pragma unroll
    for(int j=0;j<16;j++){
        float4 v = p[j*16];
        acc.x += v.x; acc.y += v.y; acc.z += v.z; acc.w += v.w;
    }
    ((float4*)out)[t*16 + c4] = acc;
}

// ---------------- launch -------------------------------------------------------
extern "C" void kernel_launch(void* const* d_in, const int* in_sizes, int n_in,
                              void* d_out, int out_size){
    const float* x    = (const float*)d_in[0];
    const float* ctrs = (const float*)d_in[1];
    const float* Wv   = (const float*)d_in[2];
    const float* Ov   = (const float*)d_in[3];
    float* out = (float*)d_out;

    const int FUSED_SMEM = (32*64 + 32*512)*4;   // 72 KB
    cudaFuncSetAttribute(k_fused, cudaFuncAttributeMaxDynamicSharedMemorySize,
                         FUSED_SMEM);

    k_prep_t<<<128, 256>>>(ctrs);
    k_prep_c<<<2, 256>>>(ctrs);
    k_prep_z<<<2, 256>>>();
    k_fused <<<512, 512, FUSED_SMEM>>>(x);   // launch #4 -> ncu capture target
    k_ss    <<<512, 512>>>();
    k_gemm  <<<444, 256>>>(x, Wv, Ov);
    k_reduce<<<1024, 256>>>(out);
}